// round 5
// baseline (speedup 1.0000x reference)
#include <cuda_runtime.h>
#include <math.h>
#include <stdint.h>

// Problem dims (fixed)
#define NT 2048
#define NB 64
#define NI 256
#define NH 512
#define NG 2048
#define GRID_B 128   // 32 unit-groups x 4 batch-groups, 1 CTA/SM, single wave
#define NWARP 16
#define KSL 32       // k rows per warp slice

// Scratch (__device__ globals; no allocation allowed)
__device__ float g_xw[(size_t)NT * NG * NB];   // [t][col][b]
__device__ float g_h[2 * NH * NB];             // [buf][k][b]
__device__ unsigned g_bar_count[4 * 32];       // per batch-group, padded
__device__ unsigned g_bar_gen[4 * 32];

__device__ __forceinline__ float fast_sigmoid(float x) {
    return __fdividef(1.0f, 1.0f + __expf(-x));
}
__device__ __forceinline__ float fast_tanh(float x) {
    float t = __expf(2.0f * x);
    return 1.0f - __fdividef(2.0f, t + 1.0f);
}

// ---- packed f32x2 helpers ----
__device__ __forceinline__ unsigned long long fma2(unsigned long long a,
                                                   unsigned long long b,
                                                   unsigned long long c) {
    unsigned long long d;
    asm("fma.rn.f32x2 %0, %1, %2, %3;" : "=l"(d) : "l"(a), "l"(b), "l"(c));
    return d;
}
__device__ __forceinline__ unsigned long long pack2(float x, float y) {
    unsigned long long r;
    asm("mov.b64 %0, {%1, %2};" : "=l"(r) : "f"(x), "f"(y));
    return r;
}
__device__ __forceinline__ float2 unpack2(unsigned long long v) {
    float2 f;
    asm("mov.b64 {%0, %1}, %2;" : "=f"(f.x), "=f"(f.y) : "l"(v));
    return f;
}

// Barrier across the 32 co-resident CTAs of one batch-group (proven R4 pattern).
__device__ __forceinline__ void group_barrier(int grp) {
    __syncthreads();
    if (threadIdx.x == 0) {
        volatile unsigned* genp = &g_bar_gen[grp * 32];
        unsigned my = *genp;
        __threadfence();                       // release: publish h writes
        if (atomicAdd(&g_bar_count[grp * 32], 1u) == 31u) {
            atomicExch(&g_bar_count[grp * 32], 0u);
            __threadfence();
            *genp = my + 1;
        } else {
            while (*genp == my) { __nanosleep(32); }
        }
        __threadfence();                       // acquire
    }
    __syncthreads();
}

// ---------------- Phase 1: xW = x @ Wi + B, output TRANSPOSED [t][col][b] ----------------
__global__ void __launch_bounds__(256, 2)
xw_gemm_kernel(const float* __restrict__ x, const float* __restrict__ Wi,
               const float* __restrict__ bias) {
    __shared__ __align__(16) float As[8][132];
    __shared__ __align__(16) float Bs[8][128];

    const int tid = threadIdx.x;
    const int tx = tid & 15, ty = tid >> 4;
    const int bm = blockIdx.y << 7, bn = blockIdx.x << 7;
    const int lrow = tid >> 1, lk = (tid & 1) << 2;
    const int brow = tid >> 5, bcol = (tid & 31) << 2;

    unsigned long long acc2[8][4];
    #pragma unroll
    for (int i = 0; i < 8; i++)
        #pragma unroll
        for (int j = 0; j < 4; j++) acc2[i][j] = 0ull;

    for (int kt = 0; kt < NI; kt += 8) {
        float4 av = *reinterpret_cast<const float4*>(x + (size_t)(bm + lrow) * NI + kt + lk);
        float4 bv = *reinterpret_cast<const float4*>(Wi + (size_t)(kt + brow) * NG + bn + bcol);
        As[lk + 0][lrow] = av.x;
        As[lk + 1][lrow] = av.y;
        As[lk + 2][lrow] = av.z;
        As[lk + 3][lrow] = av.w;
        *reinterpret_cast<float4*>(&Bs[brow][bcol]) = bv;
        __syncthreads();
        #pragma unroll
        for (int kk = 0; kk < 8; kk++) {
            float4 t0 = *reinterpret_cast<const float4*>(&As[kk][ty << 3]);
            float4 t1 = *reinterpret_cast<const float4*>(&As[kk][(ty << 3) + 4]);
            const ulonglong2* brow2 = reinterpret_cast<const ulonglong2*>(&Bs[kk][tx << 3]);
            ulonglong2 bv0 = brow2[0], bv1 = brow2[1];
            unsigned long long b2[4] = {bv0.x, bv0.y, bv1.x, bv1.y};
            float a[8] = {t0.x, t0.y, t0.z, t0.w, t1.x, t1.y, t1.z, t1.w};
            #pragma unroll
            for (int i = 0; i < 8; i++) {
                unsigned long long ap = pack2(a[i], a[i]);
                #pragma unroll
                for (int j = 0; j < 4; j++)
                    acc2[i][j] = fma2(ap, b2[j], acc2[i][j]);
            }
        }
        __syncthreads();
    }

    float4 bb0 = *reinterpret_cast<const float4*>(bias + bn + (tx << 3));
    float4 bb1 = *reinterpret_cast<const float4*>(bias + bn + (tx << 3) + 4);
    const float bb[8] = {bb0.x, bb0.y, bb0.z, bb0.w, bb1.x, bb1.y, bb1.z, bb1.w};

    const int t_idx = (bm >> 6) + (ty >> 3);
    const int b_base = (ty & 7) << 3;
    float o[8][8];
    #pragma unroll
    for (int i = 0; i < 8; i++)
        #pragma unroll
        for (int p = 0; p < 4; p++) {
            float2 v = unpack2(acc2[i][p]);
            o[i][2 * p] = v.x + bb[2 * p];
            o[i][2 * p + 1] = v.y + bb[2 * p + 1];
        }
    #pragma unroll
    for (int j = 0; j < 8; j++) {
        int col = bn + (tx << 3) + j;
        float* dst = g_xw + ((size_t)t_idx * NG + col) * NB + b_base;
        *reinterpret_cast<float4*>(dst)     = make_float4(o[0][j], o[1][j], o[2][j], o[3][j]);
        *reinterpret_cast<float4*>(dst + 4) = make_float4(o[4][j], o[5][j], o[6][j], o[7][j]);
    }
}

// ---------------- Phase 2: persistent recurrence ----------------
// CTA (ug, bgp): units 16ug..+15 (all 4 gates = 64 cols), batches 16bgp..+15.
// 512 threads = 16 warps; warp wrp owns k-slice [32*wrp, 32*wrp+32):
//   stages own h rows (syncwarp only), lane (cg,bq): cols 8cg..+7, batches 4bq..+3.
// SMEM: sWh [512][64] 128KB | shT [512][16] 32KB (sG aliased) | sRed [16][4][16][16] 64KB.
#define SMEM_FLOATS (NH * 64 + NH * 16 + NWARP * 1024)

__global__ void __launch_bounds__(512, 1)
lstm_rec_kernel(const float* __restrict__ Wh, float* __restrict__ out, int write_state) {
    extern __shared__ float smem[];
    float* sWh  = smem;                 // [k][c] c = gt*16+u16
    float* shT  = sWh + NH * 64;        // [k][16 batches]; first 2048 floats alias sG
    float* sRed = shT + NH * 16;        // [w][g][b16][u16]
    float* sG   = shT;                  // [wh][g][b16][u16] half-sums (2048 floats)

    const int tid = threadIdx.x;
    const int wrp = tid >> 5;
    const int lane = tid & 31;
    const int ug = blockIdx.x >> 2;
    const int bgp = blockIdx.x & 3;

    // Load Wh slice once: c = gt*16+u16 -> global col gt*512 + ug*16 + u16.
    for (int idx = tid; idx < NH * 64; idx += 512) {
        int k = idx >> 6, c = idx & 63;
        int gcol = ((c >> 4) << 9) + (ug << 4) + (c & 15);
        sWh[idx] = Wh[(size_t)k * NG + gcol];
    }
    // Zero own slice of h buffer 0.
    if (tid < 256) {
        int u = tid & 15, b = tid >> 4;
        g_h[(ug * 16 + u) * NB + bgp * 16 + b] = 0.f;
    }

    const int cg = lane >> 2;            // 8 col-groups (8 cols each)
    const int bq = lane & 3;             // 4 batch-quads
    const int g_of = cg >> 1;            // gate of this col-group
    const int u8 = (cg & 1) << 3;        // unit offset within gate

    const int u_ = tid & 15;             // reduce/cell unit
    const int b2 = (tid >> 4) & 15;      // reduce/cell batch
    const int wh = tid >> 8;             // reduce half (w 0-7 / 8-15)
    const int hrow = (ug << 4) + u_;
    const int bglob = (bgp << 4) + b2;
    float c_reg = 0.f;

    const float* wbase = sWh + (wrp * KSL) * 64 + (cg << 3);
    const float* hbase = shT + (wrp * KSL) * 16 + (bq << 2);

    for (int t = 0; t < NT; t++) {
        // Prefetch xW for this step (register, hidden behind barrier/stage/matmul).
        float xw0 = 0.f, xw1 = 0.f, xw2 = 0.f, xw3 = 0.f;
        if (tid < 256) {
            const float* xwt = g_xw + (size_t)t * ((size_t)NG * NB) + (size_t)hrow * NB + bglob;
            xw0 = __ldg(xwt);
            xw1 = __ldg(xwt + (size_t)(1 << 9) * NB);
            xw2 = __ldg(xwt + (size_t)(2 << 9) * NB);
            xw3 = __ldg(xwt + (size_t)(3 << 9) * NB);
        }

        group_barrier(bgp);              // h[t] globally visible for this batch-group

        // Warp-local staging of own 32 h rows x 16 batches (2KB).
        {
            const float* src = g_h + (t & 1) * (NH * NB) + (bgp << 4);
            const int rl = lane >> 2, part = (lane & 3) << 2;
            #pragma unroll
            for (int i = 0; i < 4; i++) {
                int row = wrp * KSL + (i << 3) + rl;
                float4 v = __ldcg(reinterpret_cast<const float4*>(src + row * NB + part));
                *reinterpret_cast<float4*>(shT + row * 16 + part) = v;
            }
        }
        __syncwarp();

        // Matmul over own 32-k slice: 4 col-pairs x 4 batches, FFMA2.
        unsigned long long acc[4][4];
        #pragma unroll
        for (int cp = 0; cp < 4; cp++)
            #pragma unroll
            for (int bb = 0; bb < 4; bb++) acc[cp][bb] = 0ull;

        #pragma unroll 4
        for (int kl = 0; kl < KSL; kl++) {
            ulonglong2 wA = *reinterpret_cast<const ulonglong2*>(wbase + kl * 64);
            ulonglong2 wB = *reinterpret_cast<const ulonglong2*>(wbase + kl * 64 + 4);
            float4 h = *reinterpret_cast<const float4*>(hbase + kl * 16);
            unsigned long long wp[4] = {wA.x, wA.y, wB.x, wB.y};
            unsigned long long hd[4] = {pack2(h.x, h.x), pack2(h.y, h.y),
                                        pack2(h.z, h.z), pack2(h.w, h.w)};
            #pragma unroll
            for (int cp = 0; cp < 4; cp++) {
                acc[cp][0] = fma2(wp[cp], hd[0], acc[cp][0]);
                acc[cp][1] = fma2(wp[cp], hd[1], acc[cp][1]);
                acc[cp][2] = fma2(wp[cp], hd[2], acc[cp][2]);
                acc[cp][3] = fma2(wp[cp], hd[3], acc[cp][3]);
            }
        }

        // Partials: sRed[w][g][b][u16], 2 STS.128 per batch.
        #pragma unroll
        for (int bb = 0; bb < 4; bb++) {
            float2 p0 = unpack2(acc[0][bb]);
            float2 p1 = unpack2(acc[1][bb]);
            float2 p2 = unpack2(acc[2][bb]);
            float2 p3 = unpack2(acc[3][bb]);
            float* dst = sRed + (wrp << 10) + (g_of << 8) + (((bq << 2) + bb) << 4) + u8;
            *reinterpret_cast<float4*>(dst)     = make_float4(p0.x, p0.y, p1.x, p1.y);
            *reinterpret_cast<float4*>(dst + 4) = make_float4(p2.x, p2.y, p3.x, p3.y);
        }
        __syncthreads();   // partials visible; shT (incl. sG alias) free for reuse

        // Half-reduce: thread (u_, b2, wh) sums w = 8wh..8wh+7 for all 4 gates.
        {
            float G0 = wh ? 0.f : xw0;
            float G1 = wh ? 0.f : xw1;
            float G2 = wh ? 0.f : xw2;
            float G3 = wh ? 0.f : xw3;
            const float* rp0 = sRed + (wh << 13) + (b2 << 4) + u_;
            #pragma unroll
            for (int w = 0; w < 8; w++) {
                const float* rp = rp0 + (w << 10);
                G0 += rp[0];
                G1 += rp[256];
                G2 += rp[512];
                G3 += rp[768];
            }
            float* gp = sG + (wh << 10) + (b2 << 4) + u_;
            gp[0] = G0;
            gp[256] = G1;
            gp[512] = G2;
            gp[768] = G3;
        }
        __syncthreads();

        // LSTM cell on tid<256: combine halves, fast activations, write h/out.
        if (tid < 256) {
            const float* gp = sG + (b2 << 4) + u_;
            float G0 = gp[0] + gp[1024];
            float G1 = gp[256] + gp[1280];
            float G2 = gp[512] + gp[1536];
            float G3 = gp[768] + gp[1792];
            float ig = fast_sigmoid(G0);
            float fg = fast_sigmoid(G1);
            float gg = fast_tanh(G2);
            float og = fast_sigmoid(G3);
            c_reg = fg * c_reg + ig * gg;
            float h = og * fast_tanh(c_reg);
            out[((size_t)t * NB + bglob) * NH + hrow] = h;
            __stcg(&g_h[((t + 1) & 1) * (NH * NB) + hrow * NB + bglob], h);
            if (write_state && t == NT - 1) {
                size_t base = (size_t)NT * NB * NH;
                out[base + (size_t)bglob * NH + hrow] = h;
                out[base + (size_t)NB * NH + (size_t)bglob * NH + hrow] = c_reg;
            }
        }
        // Next loop-top group_barrier publishes these h writes.
    }
}

extern "C" void kernel_launch(void* const* d_in, const int* in_sizes, int n_in,
                              void* d_out, int out_size) {
    const float* x  = (const float*)d_in[0];
    const float* Wi = (const float*)d_in[1];
    const float* Wh = (const float*)d_in[2];
    const float* B  = (const float*)d_in[3];
    float* out = (float*)d_out;

    const int smem_bytes = SMEM_FLOATS * (int)sizeof(float);   // 229376 B
    cudaFuncSetAttribute(lstm_rec_kernel, cudaFuncAttributeMaxDynamicSharedMemorySize, smem_bytes);

    dim3 gA(NG / 128, (NT * NB) / 128);
    xw_gemm_kernel<<<gA, 256>>>(x, Wi, B);

    const long long need_full = (long long)NT * NB * NH + 2LL * NB * NH;
    int write_state = ((long long)out_size >= need_full) ? 1 : 0;

    lstm_rec_kernel<<<GRID_B, 512, smem_bytes>>>(Wh, out, write_state);
}

// round 6
// speedup vs baseline: 1.2195x; 1.2195x over previous
#include <cuda_runtime.h>
#include <math.h>
#include <stdint.h>

// Problem dims (fixed)
#define NT 2048
#define NB 64
#define NI 256
#define NH 512
#define NG 2048
#define GRID_B 128   // 32 unit-groups x 4 batch-groups, 1 CTA/SM, single wave
#define NWARP 16
#define KSL 32       // k rows per warp slice

// Scratch (__device__ globals; no allocation allowed)
__device__ float g_xw[(size_t)NT * NG * NB];   // [t][col][b]
__device__ float g_h[2 * NH * NB];             // [buf][k][b]
__device__ unsigned g_flag[4 * 32 * 32];       // flag[(bgp*32+slice)*32]; value = t avail

__device__ __forceinline__ float fast_sigmoid(float x) {
    return __fdividef(1.0f, 1.0f + __expf(-x));
}
__device__ __forceinline__ float fast_tanh(float x) {
    float t = __expf(2.0f * x);
    return 1.0f - __fdividef(2.0f, t + 1.0f);
}

// ---- packed f32x2 helpers ----
__device__ __forceinline__ unsigned long long fma2(unsigned long long a,
                                                   unsigned long long b,
                                                   unsigned long long c) {
    unsigned long long d;
    asm("fma.rn.f32x2 %0, %1, %2, %3;" : "=l"(d) : "l"(a), "l"(b), "l"(c));
    return d;
}
__device__ __forceinline__ unsigned long long pack2(float x, float y) {
    unsigned long long r;
    asm("mov.b64 %0, {%1, %2};" : "=l"(r) : "f"(x), "f"(y));
    return r;
}
__device__ __forceinline__ float2 unpack2(unsigned long long v) {
    float2 f;
    asm("mov.b64 {%0, %1}, %2;" : "=f"(f.x), "=f"(f.y) : "l"(v));
    return f;
}
__device__ __forceinline__ unsigned ld_acquire(const unsigned* p) {
    unsigned v;
    asm volatile("ld.acquire.gpu.global.b32 %0, [%1];" : "=r"(v) : "l"(p));
    return v;
}

// Prelude: zero h buffer 0 and all flags (runs every launch/replay).
__global__ void init_kernel() {
    int i = blockIdx.x * blockDim.x + threadIdx.x;
    if (i < NH * NB) g_h[i] = 0.f;
    if (i < 4 * 32 * 32) g_flag[i] = 0u;
}

// ---------------- Phase 1: xW = x @ Wi + B, output TRANSPOSED [t][col][b] ----------------
__global__ void __launch_bounds__(256, 2)
xw_gemm_kernel(const float* __restrict__ x, const float* __restrict__ Wi,
               const float* __restrict__ bias) {
    __shared__ __align__(16) float As[8][132];
    __shared__ __align__(16) float Bs[8][128];

    const int tid = threadIdx.x;
    const int tx = tid & 15, ty = tid >> 4;
    const int bm = blockIdx.y << 7, bn = blockIdx.x << 7;
    const int lrow = tid >> 1, lk = (tid & 1) << 2;
    const int brow = tid >> 5, bcol = (tid & 31) << 2;

    unsigned long long acc2[8][4];
    #pragma unroll
    for (int i = 0; i < 8; i++)
        #pragma unroll
        for (int j = 0; j < 4; j++) acc2[i][j] = 0ull;

    for (int kt = 0; kt < NI; kt += 8) {
        float4 av = *reinterpret_cast<const float4*>(x + (size_t)(bm + lrow) * NI + kt + lk);
        float4 bv = *reinterpret_cast<const float4*>(Wi + (size_t)(kt + brow) * NG + bn + bcol);
        As[lk + 0][lrow] = av.x;
        As[lk + 1][lrow] = av.y;
        As[lk + 2][lrow] = av.z;
        As[lk + 3][lrow] = av.w;
        *reinterpret_cast<float4*>(&Bs[brow][bcol]) = bv;
        __syncthreads();
        #pragma unroll
        for (int kk = 0; kk < 8; kk++) {
            float4 t0 = *reinterpret_cast<const float4*>(&As[kk][ty << 3]);
            float4 t1 = *reinterpret_cast<const float4*>(&As[kk][(ty << 3) + 4]);
            const ulonglong2* brow2 = reinterpret_cast<const ulonglong2*>(&Bs[kk][tx << 3]);
            ulonglong2 bv0 = brow2[0], bv1 = brow2[1];
            unsigned long long b2[4] = {bv0.x, bv0.y, bv1.x, bv1.y};
            float a[8] = {t0.x, t0.y, t0.z, t0.w, t1.x, t1.y, t1.z, t1.w};
            #pragma unroll
            for (int i = 0; i < 8; i++) {
                unsigned long long ap = pack2(a[i], a[i]);
                #pragma unroll
                for (int j = 0; j < 4; j++)
                    acc2[i][j] = fma2(ap, b2[j], acc2[i][j]);
            }
        }
        __syncthreads();
    }

    float4 bb0 = *reinterpret_cast<const float4*>(bias + bn + (tx << 3));
    float4 bb1 = *reinterpret_cast<const float4*>(bias + bn + (tx << 3) + 4);
    const float bb[8] = {bb0.x, bb0.y, bb0.z, bb0.w, bb1.x, bb1.y, bb1.z, bb1.w};

    const int t_idx = (bm >> 6) + (ty >> 3);
    const int b_base = (ty & 7) << 3;
    float o[8][8];
    #pragma unroll
    for (int i = 0; i < 8; i++)
        #pragma unroll
        for (int p = 0; p < 4; p++) {
            float2 v = unpack2(acc2[i][p]);
            o[i][2 * p] = v.x + bb[2 * p];
            o[i][2 * p + 1] = v.y + bb[2 * p + 1];
        }
    #pragma unroll
    for (int j = 0; j < 8; j++) {
        int col = bn + (tx << 3) + j;
        float* dst = g_xw + ((size_t)t_idx * NG + col) * NB + b_base;
        *reinterpret_cast<float4*>(dst)     = make_float4(o[0][j], o[1][j], o[2][j], o[3][j]);
        *reinterpret_cast<float4*>(dst + 4) = make_float4(o[4][j], o[5][j], o[6][j], o[7][j]);
    }
}

// ---------------- Phase 2: persistent recurrence, flag-synced ----------------
// CTA (ug, bgp): units 16ug..+15 (all 4 gates = 64 cols), batches 16bgp..+15.
// 512 threads = 16 warps; warp wrp owns k-slice [32wrp, 32wrp+32).
// Half-warp hl waits flag[2wrp+hl] (16-row slice), stages it, FFMA2 matmul.
// No global barrier: flags ≥ t observed by all warps before any h_{t+1} write
// proves all CTAs finished step t-1 => double buffer safe.
// SMEM: sWh [512][64] 128KB | shT [512][16] 32KB (sG aliased) | sRed 64KB.
#define SMEM_FLOATS (NH * 64 + NH * 16 + NWARP * 1024)

__global__ void __launch_bounds__(512, 1)
lstm_rec_kernel(const float* __restrict__ Wh, float* __restrict__ out, int write_state) {
    extern __shared__ float smem[];
    float* sWh  = smem;                 // [k][c] c = gt*16+u16
    float* shT  = sWh + NH * 64;        // [k][16 batches]; first 2048 floats alias sG
    float* sRed = shT + NH * 16;        // [w][g][b16][u16]
    float* sG   = shT;                  // [wh][g][b16][u16] half-sums

    const int tid = threadIdx.x;
    const int wrp = tid >> 5;
    const int lane = tid & 31;
    const int ug = blockIdx.x >> 2;
    const int bgp = blockIdx.x & 3;

    // Load Wh slice once: c = gt*16+u16 -> global col gt*512 + ug*16 + u16.
    for (int idx = tid; idx < NH * 64; idx += 512) {
        int k = idx >> 6, c = idx & 63;
        int gcol = ((c >> 4) << 9) + (ug << 4) + (c & 15);
        sWh[idx] = Wh[(size_t)k * NG + gcol];
    }

    const int cg = lane >> 2;            // 8 col-groups (8 cols each)
    const int bq = lane & 3;             // 4 batch-quads
    const int g_of = cg >> 1;
    const int u8 = (cg & 1) << 3;

    const int hl = lane >> 4;            // half-warp: 16-row sub-slice
    const int l16 = lane & 15;
    const int slice = (wrp << 1) + hl;   // 0..31: h rows [16*slice, 16*slice+16)
    const unsigned* flagp = &g_flag[(bgp * 32 + slice) * 32];

    const int u_ = tid & 15;             // reduce/cell unit
    const int b2 = (tid >> 4) & 15;      // reduce/cell batch
    const int wh = tid >> 8;             // reduce half
    const int hrow = (ug << 4) + u_;
    const int bglob = (bgp << 4) + b2;
    float c_reg = 0.f;

    const unsigned* myflag = &g_flag[(bgp * 32 + ug) * 32];

    const float* wbase = sWh + (wrp * KSL) * 64 + (cg << 3);
    const float* hbase = shT + (wrp * KSL) * 16 + (bq << 2);

    __syncthreads();

    for (int t = 0; t < NT; t++) {
        // Prefetch xW for this step (register, hidden behind wait/stage/matmul).
        float xw0 = 0.f, xw1 = 0.f, xw2 = 0.f, xw3 = 0.f;
        if (tid < 256) {
            const float* xwt = g_xw + (size_t)t * ((size_t)NG * NB) + (size_t)hrow * NB + bglob;
            xw0 = __ldg(xwt);
            xw1 = __ldg(xwt + (size_t)(1 << 9) * NB);
            xw2 = __ldg(xwt + (size_t)(2 << 9) * NB);
            xw3 = __ldg(xwt + (size_t)(3 << 9) * NB);
        }

        // Wait for own 16-row h sub-slice (acquire), then stage it (2KB/half).
        if (ld_acquire(flagp) < (unsigned)t) {
            do { __nanosleep(20); } while (ld_acquire(flagp) < (unsigned)t);
        }
        {
            const float* src = g_h + (t & 1) * (NH * NB) + (bgp << 4);
            const int rl = l16 >> 2, part = (l16 & 3) << 2;
            #pragma unroll
            for (int i = 0; i < 4; i++) {
                int row = (slice << 4) + (i << 2) + rl;
                float4 v = __ldcg(reinterpret_cast<const float4*>(src + row * NB + part));
                *reinterpret_cast<float4*>(shT + row * 16 + part) = v;
            }
        }
        __syncwarp();

        // Matmul over own 32-k slice: 4 col-pairs x 4 batches, FFMA2.
        unsigned long long acc[4][4];
        #pragma unroll
        for (int cp = 0; cp < 4; cp++)
            #pragma unroll
            for (int bb = 0; bb < 4; bb++) acc[cp][bb] = 0ull;

        #pragma unroll 4
        for (int kl = 0; kl < KSL; kl++) {
            ulonglong2 wA = *reinterpret_cast<const ulonglong2*>(wbase + kl * 64);
            ulonglong2 wB = *reinterpret_cast<const ulonglong2*>(wbase + kl * 64 + 4);
            float4 h = *reinterpret_cast<const float4*>(hbase + kl * 16);
            unsigned long long wp[4] = {wA.x, wA.y, wB.x, wB.y};
            unsigned long long hd[4] = {pack2(h.x, h.x), pack2(h.y, h.y),
                                        pack2(h.z, h.z), pack2(h.w, h.w)};
            #pragma unroll
            for (int cp = 0; cp < 4; cp++) {
                acc[cp][0] = fma2(wp[cp], hd[0], acc[cp][0]);
                acc[cp][1] = fma2(wp[cp], hd[1], acc[cp][1]);
                acc[cp][2] = fma2(wp[cp], hd[2], acc[cp][2]);
                acc[cp][3] = fma2(wp[cp], hd[3], acc[cp][3]);
            }
        }

        // Partials: sRed[w][g][b][u16].
        #pragma unroll
        for (int bb = 0; bb < 4; bb++) {
            float2 p0 = unpack2(acc[0][bb]);
            float2 p1 = unpack2(acc[1][bb]);
            float2 p2 = unpack2(acc[2][bb]);
            float2 p3 = unpack2(acc[3][bb]);
            float* dst = sRed + (wrp << 10) + (g_of << 8) + (((bq << 2) + bb) << 4) + u8;
            *reinterpret_cast<float4*>(dst)     = make_float4(p0.x, p0.y, p1.x, p1.y);
            *reinterpret_cast<float4*>(dst + 4) = make_float4(p2.x, p2.y, p3.x, p3.y);
        }
        __syncthreads();   // all flags >= t observed by all warps beyond this point

        // Half-reduce: thread (u_, b2, wh) sums w = 8wh..8wh+7 for all 4 gates.
        {
            float G0 = wh ? 0.f : xw0;
            float G1 = wh ? 0.f : xw1;
            float G2 = wh ? 0.f : xw2;
            float G3 = wh ? 0.f : xw3;
            const float* rp0 = sRed + (wh << 13) + (b2 << 4) + u_;
            #pragma unroll
            for (int w = 0; w < 8; w++) {
                const float* rp = rp0 + (w << 10);
                G0 += rp[0];
                G1 += rp[256];
                G2 += rp[512];
                G3 += rp[768];
            }
            float* gp = sG + (wh << 10) + (b2 << 4) + u_;
            gp[0] = G0;
            gp[256] = G1;
            gp[512] = G2;
            gp[768] = G3;
        }
        __syncthreads();

        // LSTM cell on tid<256: combine halves, fast activations, write h/out.
        if (tid < 256) {
            const float* gp = sG + (b2 << 4) + u_;
            float G0 = gp[0] + gp[1024];
            float G1 = gp[256] + gp[1280];
            float G2 = gp[512] + gp[1536];
            float G3 = gp[768] + gp[1792];
            float ig = fast_sigmoid(G0);
            float fg = fast_sigmoid(G1);
            float gg = fast_tanh(G2);
            float og = fast_sigmoid(G3);
            c_reg = fg * c_reg + ig * gg;
            float h = og * fast_tanh(c_reg);
            out[((size_t)t * NB + bglob) * NH + hrow] = h;
            __stcg(&g_h[((t + 1) & 1) * (NH * NB) + hrow * NB + bglob], h);
            if (write_state && t == NT - 1) {
                size_t base = (size_t)NT * NB * NH;
                out[base + (size_t)bglob * NH + hrow] = h;
                out[base + (size_t)NB * NH + (size_t)bglob * NH + hrow] = c_reg;
            }
        }
        __syncthreads();   // all cell h-writes done; also fences shT/sG reuse

        // Publish h_{t+1} for this CTA's slice.
        if (tid == 0) {
            __threadfence();
            asm volatile("st.release.gpu.global.b32 [%0], %1;"
                         :: "l"(myflag), "r"((unsigned)(t + 1)) : "memory");
        }
    }
}

extern "C" void kernel_launch(void* const* d_in, const int* in_sizes, int n_in,
                              void* d_out, int out_size) {
    const float* x  = (const float*)d_in[0];
    const float* Wi = (const float*)d_in[1];
    const float* Wh = (const float*)d_in[2];
    const float* B  = (const float*)d_in[3];
    float* out = (float*)d_out;

    const int smem_bytes = SMEM_FLOATS * (int)sizeof(float);   // 229376 B
    cudaFuncSetAttribute(lstm_rec_kernel, cudaFuncAttributeMaxDynamicSharedMemorySize, smem_bytes);

    init_kernel<<<32, 1024>>>();   // zero h0 + flags (every launch/replay)

    dim3 gA(NG / 128, (NT * NB) / 128);
    xw_gemm_kernel<<<gA, 256>>>(x, Wi, B);

    const long long need_full = (long long)NT * NB * NH + 2LL * NB * NH;
    int write_state = ((long long)out_size >= need_full) ? 1 : 0;

    lstm_rec_kernel<<<GRID_B, 512, smem_bytes>>>(Wh, out, write_state);
}